// round 9
// baseline (speedup 1.0000x reference)
#include <cuda_runtime.h>
#include <cstdint>

typedef unsigned long long ull;

#define NN 512
#define F 16
#define TE 128            // tile edge
#define RDS 36            // per-row duplicated storage stride (floats)
#define CS 132            // sCol stride (floats)
#define XS 133            // transpose strip stride (odd => conflict-free cols)
#define NTHREADS 256

struct ull2_t { ull x, y; };

__device__ __forceinline__ ull pack2(float lo, float hi) {
    ull r;
    asm("mov.b64 %0, {%1, %2};" : "=l"(r) : "f"(lo), "f"(hi));
    return r;
}
__device__ __forceinline__ void unpack2(ull v, float& lo, float& hi) {
    asm("mov.b64 {%0, %1}, %2;" : "=f"(lo), "=f"(hi) : "l"(v));
}
__device__ __forceinline__ ull fma2(ull a, ull b, ull c) {
    ull d;
    asm("fma.rn.f32x2 %0, %1, %2, %3;" : "=l"(d) : "l"(a), "l"(b), "l"(c));
    return d;
}
__device__ __forceinline__ ull add2(ull a, ull b) {
    ull d;
    asm("add.rn.f32x2 %0, %1, %2;" : "=l"(d) : "l"(a), "l"(b));
    return d;
}

// exp(-0.1*sqrt(max(v,1e-6))) ; result always in (0,1) so clip is free
__device__ __forceinline__ float gauss1(float v) {
    float t = fmaxf(v, 1e-6f);
    float d;
    asm("sqrt.approx.f32 %0, %1;" : "=f"(d) : "f"(t));
    float xx = d * -0.14426950408889634f;   // -0.1 * log2(e)
    float e;
    asm("ex2.approx.f32 %0, %1;" : "=f"(e) : "f"(xx));
    return e;
}

__global__ void __launch_bounds__(NTHREADS, 2)
npg_sym128(const float* __restrict__ x, const float* __restrict__ msk,
           float* __restrict__ out) {
    __shared__ __align__(16) float sRowD[TE * RDS];      // rows: (a,a) f-pair-contig
    __shared__ __align__(16) float sCol[F * CS];         // cols, f-major plain
    __shared__ __align__(16) float sNaRD[2 * TE];        // na rows, duplicated pairs
    __shared__ __align__(16) float sNaC[TE + 4];         // na cols, plain
    __shared__ __align__(16) float sXS[32 * XS];         // mirror transpose strip

    const int tid = threadIdx.x;
    const int bk  = blockIdx.y;

    // upper-triangular pair (ti <= tj) of the 4x4 tile grid (10 pairs)
    int t = blockIdx.x, ti = 0;
    while (t >= 4 - ti) { t -= 4 - ti; ++ti; }
    const int tj = ti + t;
    const int rbase = ti * TE;
    const int cbase = tj * TE;

    // ---- stage A = x*msk (rows duplicated, cols plain) + fused na ----
    const float4* xb = reinterpret_cast<const float4*>(x + (size_t)bk * NN * F);
    const float*  mb = msk + (size_t)bk * NN;
    #pragma unroll
    for (int k = 0; k < 2; k++) {
        int i  = k * NTHREADS + tid;
        int n  = i >> 2;                 // node 0..127
        int fq = i & 3;                  // f quad
        int f0 = fq << 2;

        float4 v = __ldg(&xb[(rbase + n) * 4 + fq]);
        float  m = __ldg(&mb[rbase + n]);
        float r0 = v.x * m, r1 = v.y * m, r2 = v.z * m, r3 = v.w * m;
        ull* rd = reinterpret_cast<ull*>(&sRowD[n * RDS + (f0 << 1)]);
        rd[0] = pack2(r0, r0);
        rd[1] = pack2(r1, r1);
        rd[2] = pack2(r2, r2);
        rd[3] = pack2(r3, r3);
        float s = fmaf(r0, r0, fmaf(r1, r1, fmaf(r2, r2, r3 * r3)));
        s += __shfl_xor_sync(~0u, s, 1);
        s += __shfl_xor_sync(~0u, s, 2);
        if (fq == 0) *reinterpret_cast<ull*>(&sNaRD[2 * n]) = pack2(s, s);

        float4 w  = __ldg(&xb[(cbase + n) * 4 + fq]);
        float  mc = __ldg(&mb[cbase + n]);
        float c0v = w.x * mc, c1v = w.y * mc, c2v = w.z * mc, c3v = w.w * mc;
        sCol[(f0 + 0) * CS + n] = c0v;
        sCol[(f0 + 1) * CS + n] = c1v;
        sCol[(f0 + 2) * CS + n] = c2v;
        sCol[(f0 + 3) * CS + n] = c3v;
        float sc = fmaf(c0v, c0v, fmaf(c1v, c1v, fmaf(c2v, c2v, c3v * c3v)));
        sc += __shfl_xor_sync(~0u, sc, 1);
        sc += __shfl_xor_sync(~0u, sc, 2);
        if (fq == 0) sNaC[n] = sc;
    }
    __syncthreads();

    const int cx = tid & 31;      // 32 col-threads * 4 cols = 128
    const int ry = tid >> 5;      // 8 row-groups * 16 rows = 128 (warp-uniform)
    const int c0 = cx << 2;

    // ---- cache 4 cols x 16 f as packed pairs (LDS.128, zero movs) ----
    ull ccA[F], ccB[F];
    #pragma unroll
    for (int f = 0; f < F; f++) {
        ull2_t u = *reinterpret_cast<const ull2_t*>(&sCol[f * CS + c0]);
        ccA[f] = u.x;
        ccB[f] = u.y;
    }
    ull nacA, nacB;
    {
        float4 q = *reinterpret_cast<const float4*>(&sNaC[c0]);
        nacA = pack2(q.x, q.y);
        nacB = pack2(q.z, q.w);
    }

    float* outb = out + (size_t)bk * NN * NN;
    const ull NEG2 = pack2(-2.f, -2.f);

    const float* rbp = &sRowD[(ry << 4) * RDS];                 // this group's rows
    const ull*   nrp = reinterpret_cast<const ull*>(&sNaRD[(ry << 4) * 2]);
    float* op = outb + (size_t)(rbase + (ry << 4)) * NN + cbase + c0;

    // ---- 16 rows x 4 cols; 2 rows in flight; immediate-offset addressing ----
    #pragma unroll 4
    for (int i = 0; i < 16; i += 2) {
        ull nar0 = nrp[i];
        ull nar1 = nrp[i + 1];
        ull s0A = add2(nar0, nacA), s0B = add2(nar0, nacB);
        ull s1A = add2(nar1, nacA), s1B = add2(nar1, nacB);

        ull a00 = 0ULL, a01 = 0ULL, a10 = 0ULL, a11 = 0ULL;
        #pragma unroll
        for (int k = 0; k < 8; k++) {
            // LDS.128 -> ((a_f,a_f),(a_f+1,a_f+1)) ready-packed broadcast
            ull2_t w0 = *reinterpret_cast<const ull2_t*>(&rbp[i * RDS + 4 * k]);
            ull2_t w1 = *reinterpret_cast<const ull2_t*>(&rbp[(i + 1) * RDS + 4 * k]);
            a00 = fma2(w0.x, ccA[2 * k],     a00);
            a01 = fma2(w0.x, ccB[2 * k],     a01);
            a10 = fma2(w1.x, ccA[2 * k],     a10);
            a11 = fma2(w1.x, ccB[2 * k],     a11);
            a00 = fma2(w0.y, ccA[2 * k + 1], a00);
            a01 = fma2(w0.y, ccB[2 * k + 1], a01);
            a10 = fma2(w1.y, ccA[2 * k + 1], a10);
            a11 = fma2(w1.y, ccB[2 * k + 1], a11);
        }

        ull v0A = fma2(a00, NEG2, s0A);
        ull v0B = fma2(a01, NEG2, s0B);
        ull v1A = fma2(a10, NEG2, s1A);
        ull v1B = fma2(a11, NEG2, s1B);

        float p0, p1, p2, p3, q0, q1, q2, q3;
        unpack2(v0A, p0, p1);
        unpack2(v0B, p2, p3);
        unpack2(v1A, q0, q1);
        unpack2(v1B, q2, q3);

        float4 o0, o1;
        o0.x = gauss1(p0); o0.y = gauss1(p1); o0.z = gauss1(p2); o0.w = gauss1(p3);
        o1.x = gauss1(q0); o1.y = gauss1(q1); o1.z = gauss1(q2); o1.w = gauss1(q3);

        *reinterpret_cast<float4*>(op + (size_t)i * NN)       = o0;   // base+imm
        *reinterpret_cast<float4*>(op + (size_t)(i + 1) * NN) = o1;
    }

    // ---- mirror: re-read own L2-hot tile, transpose via smem, all .128 gmem ----
    if (ti != tj) {
        __syncthreads();   // straight writes visible block-wide
        #pragma unroll 1
        for (int bi = 0; bi < 4; bi++) {
            const float* src = outb + (size_t)(rbase + 32 * bi) * NN + cbase;
            #pragma unroll
            for (int it = 0; it < 4; it++) {
                int idx4 = it * NTHREADS + tid;
                int rr = idx4 >> 5;                // 0..31
                int c4 = (idx4 & 31) << 2;         // 0..124
                float4 v = *reinterpret_cast<const float4*>(&src[(size_t)rr * NN + c4]);
                float* d = &sXS[rr * XS + c4];     // lanes stride 4 -> conflict-free
                d[0] = v.x; d[1] = v.y; d[2] = v.z; d[3] = v.w;
            }
            __syncthreads();
            float* dstb = outb + (size_t)cbase * NN + rbase + 32 * bi;
            #pragma unroll
            for (int it = 0; it < 4; it++) {
                int idx4 = it * NTHREADS + tid;
                int cc = idx4 >> 3;                // mirror row 0..127
                int q  = (idx4 & 7) << 2;          // rr quad 0,4..28
                float4 w;
                w.x = sXS[(q + 0) * XS + cc];      // odd stride: conflict-free
                w.y = sXS[(q + 1) * XS + cc];
                w.z = sXS[(q + 2) * XS + cc];
                w.w = sXS[(q + 3) * XS + cc];
                *reinterpret_cast<float4*>(&dstb[(size_t)cc * NN + q]) = w;
            }
            __syncthreads();
        }
    }
}

extern "C" void kernel_launch(void* const* d_in, const int* in_sizes, int n_in,
                              void* d_out, int out_size) {
    const float* x   = (const float*)d_in[0];   // (8,64,512,16)
    const float* msk = (const float*)d_in[1];   // (8,64,512,1)
    float* out = (float*)d_out;                 // (8,64,512,512,1)

    int bk_total = in_sizes[0] / (NN * F);      // 512
    dim3 grid(10, bk_total);                    // 10 upper-tri 128-tiles x 512 bins
    npg_sym128<<<grid, NTHREADS>>>(x, msk, out);
}